// round 4
// baseline (speedup 1.0000x reference)
#include <cuda_runtime.h>
#include <cstdint>

// ---------------------------------------------------------------------------
// SpikeFP32Embedding: out[tok] = weight_pulse[token_ids[tok]]
//   token_ids   : [16384]  (int64 per reference; int32 if JAX x64 was off)
//   weight_pulse: [32768, 128, 32] fp32  -> 16 KB per row
//   out         : [16384, 128, 32] fp32
// Pure row gather, memory-bound. Traffic floor: ~205 MB unique reads
// (L2 already captures duplicate rows, measured) + 256 MB writes.
//
// R3 (re-run; previous attempt hit a container-infra failure, no kernel data):
// raise read MLP. 128 threads/row, 8 float4/thread, all 8 loads front-batched
// before any store (MLP_p1: 4 -> 8). Detection is per-warp parallel
// (8 lanes + __any_sync), no __syncthreads on the critical path.
// ---------------------------------------------------------------------------

#define ROW_F4   1024   // 128*32 floats = 1024 float4 per row
#define THREADS  128
#define F4_PER_T (ROW_F4 / THREADS)   // 8

__global__ __launch_bounds__(THREADS)
void gather_rows_kernel(const void* __restrict__ ids,
                        const float4* __restrict__ w,
                        float4* __restrict__ out) {
    // ---- per-warp inline dtype detection ------------------------------------
    // u64 words 1..8 of the id buffer: under int64 layout these are tokens
    // 1..8 (< 2^15); under int32 packing any nonzero token at odd index 3..17
    // makes a word >= 2^32. 8 parallel broadcast loads (L2-hit after first
    // warp) + one ballot. False-negative prob ~ (1/32000)^8.
    const int lane = threadIdx.x & 31;
    bool hi = false;
    if (lane >= 1 && lane <= 8)
        hi = (__ldg((const unsigned long long*)ids + lane) >= 32768ULL);
    const bool ids_i64 = !__any_sync(0xffffffffu, hi);

    // ---- row gather ----------------------------------------------------------
    const int tok = blockIdx.x;

    long long id;
    if (ids_i64) {
        id = __ldg((const long long*)ids + tok);
    } else {
        id = (long long)__ldg((const int*)ids + tok);
    }

    const float4* __restrict__ src = w   + (size_t)id  * ROW_F4;
    float4*       __restrict__ dst = out + (size_t)tok * ROW_F4;

    const int t = threadIdx.x;

    // Front-batch all 8 independent loads, then drain stores.
    float4 v[F4_PER_T];
#pragma unroll
    for (int j = 0; j < F4_PER_T; j++)
        v[j] = __ldg(&src[t + j * THREADS]);
#pragma unroll
    for (int j = 0; j < F4_PER_T; j++)
        __stwt(&dst[t + j * THREADS], v[j]);   // streaming store: output has
                                               // zero reuse, keep L2 for rows
}

extern "C" void kernel_launch(void* const* d_in, const int* in_sizes, int n_in,
                              void* d_out, int out_size) {
    const void*   ids = d_in[0];
    const float4* w   = (const float4*)d_in[1];
    float4*       out = (float4*)d_out;

    const int n_tokens = in_sizes[0];   // 16384

    gather_rows_kernel<<<n_tokens, THREADS>>>(ids, w, out);
}

// round 5
// speedup vs baseline: 1.0160x; 1.0160x over previous
#include <cuda_runtime.h>
#include <cstdint>

// ---------------------------------------------------------------------------
// SpikeFP32Embedding: out[tok] = weight_pulse[token_ids[tok]]
//   token_ids   : [16384]  (int64 per reference; int32 if JAX x64 was off)
//   weight_pulse: [32768, 128, 32] fp32  -> 16 KB per row
//   out         : [16384, 128, 32] fp32
// Pure row gather, memory-bound. Traffic is at the floor (~212 MB reads =
// unique-row minimum, 256 MB mandatory writes); achieved BW plateaus at
// ~6.05 TB/s with either MLP=4 or MLP=8, so concurrency is NOT the limiter.
//
// R5 experiment: store policy. __stwt (write-through) may defeat L2-side
// write batching; __stcs (streaming evict-first) keeps full-line L2
// writeback coalescing without polluting L2 for the gathered rows.
// ---------------------------------------------------------------------------

#define ROW_F4   1024   // 128*32 floats = 1024 float4 per row
#define THREADS  256
#define F4_PER_T (ROW_F4 / THREADS)   // 4

__global__ __launch_bounds__(THREADS)
void gather_rows_kernel(const void* __restrict__ ids,
                        const float4* __restrict__ w,
                        float4* __restrict__ out) {
    // ---- per-warp inline dtype detection ------------------------------------
    // u64 words 1..8 of the id buffer: under int64 layout these are tokens
    // 1..8 (< 2^15); under int32 packing any nonzero token at odd index 3..17
    // makes a word >= 2^32. 8 parallel broadcast loads (L2-hit after the
    // first warp) + one ballot. False-negative prob ~ (1/32000)^8.
    const int lane = threadIdx.x & 31;
    bool hi = false;
    if (lane >= 1 && lane <= 8)
        hi = (__ldg((const unsigned long long*)ids + lane) >= 32768ULL);
    const bool ids_i64 = !__any_sync(0xffffffffu, hi);

    // ---- row gather ----------------------------------------------------------
    const int tok = blockIdx.x;

    long long id;
    if (ids_i64) {
        id = __ldg((const long long*)ids + tok);
    } else {
        id = (long long)__ldg((const int*)ids + tok);
    }

    const float4* __restrict__ src = w   + (size_t)id  * ROW_F4;
    float4*       __restrict__ dst = out + (size_t)tok * ROW_F4;

    const int t = threadIdx.x;

    // Front-batch the 4 independent loads, then drain stores.
    float4 v[F4_PER_T];
#pragma unroll
    for (int j = 0; j < F4_PER_T; j++)
        v[j] = __ldg(&src[t + j * THREADS]);
#pragma unroll
    for (int j = 0; j < F4_PER_T; j++)
        __stcs(&dst[t + j * THREADS], v[j]);   // streaming evict-first store:
                                               // L2 write-coalescing stays on,
                                               // weight rows keep L2 capacity
}

extern "C" void kernel_launch(void* const* d_in, const int* in_sizes, int n_in,
                              void* d_out, int out_size) {
    const void*   ids = d_in[0];
    const float4* w   = (const float4*)d_in[1];
    float4*       out = (float4*)d_out;

    const int n_tokens = in_sizes[0];   // 16384

    gather_rows_kernel<<<n_tokens, THREADS>>>(ids, w, out);
}